// round 6
// baseline (speedup 1.0000x reference)
#include <cuda_runtime.h>

// ---------------- scratch (no allocation allowed) ----------------
#define N2MAX  100096
#define E2MAX  1200128
#define GMAX   2048

__device__ float g_bufA[N2MAX * 128];
__device__ float g_bufB[N2MAX * 128];
__device__ int   g_deg[N2MAX];
__device__ float g_dinv[N2MAX];
__device__ float g_invdeg[N2MAX];
__device__ int   g_offs[N2MAX + 1];
__device__ int   g_cursor[N2MAX];
__device__ int   g_bsum[512];
__device__ int   g_bscan[512];
__device__ int   g_csrc[E2MAX];
__device__ float g_cnorm[E2MAX];
// stats layout:
//  L1: branch b at b*512 {sum128, sumsq128, scale128, shift128}
//  L2: branch b at 1024 + b*256 {sum64, sumsq64, scale64, shift64}
//  head: 1536 {sum64, sumsq64, scale64, shift64}
__device__ float g_stats[2048];
__device__ float g_pool[2 * GMAX * 64];
__device__ float g_cnt[GMAX];
__device__ float g_headT[GMAX * 64];

// ---------------- init ----------------
__global__ void k_zero_all(int* deg, int nd, float* stats, int ns,
                           float* pool, int np, float* cnt, int nc) {
    int i = blockIdx.x * blockDim.x + threadIdx.x;
    if (i < nd) { deg[i] = 0; return; }
    i -= nd;
    if (i < ns) { stats[i] = 0.f; return; }
    i -= ns;
    if (i < np) { pool[i] = 0.f; return; }
    i -= np;
    if (i < nc) cnt[i] = 0.f;
}

// combined: graph-size histogram (first N threads) + in-degree histogram (next 2E)
__global__ void k_hist(const int* __restrict__ batch, int N,
                       const int* __restrict__ ei0, const int* __restrict__ ei1,
                       int E, float* __restrict__ cnt, int* __restrict__ deg) {
    int i = blockIdx.x * blockDim.x + threadIdx.x;
    if (i < N) { atomicAdd(&cnt[batch[i]], 1.f); return; }
    int e = i - N;
    if (e >= 2 * E) return;
    int d = (e < E) ? ei0[E + e] : (ei1[E + (e - E)] + N);
    atomicAdd(&deg[d], 1);
}

// ---------------- scan phase 1 (+degree finalize fused) ----------------
__global__ void k_scan1(const int* __restrict__ deg, int* __restrict__ offs,
                        int* __restrict__ bsum, float* __restrict__ dinv,
                        float* __restrict__ invdeg, int N2) {
    __shared__ int sh[256];
    int tid = threadIdx.x;
    int i = blockIdx.x * 256 + tid;
    int v = (i < N2) ? deg[i] : 0;
    if (i < N2) {
        float d = (float)v + 1.f;
        dinv[i] = rsqrtf(d);
        invdeg[i] = 1.f / d;
    }
    sh[tid] = v;
    __syncthreads();
#pragma unroll
    for (int off = 1; off < 256; off <<= 1) {
        int t = (tid >= off) ? sh[tid - off] : 0;
        __syncthreads();
        sh[tid] += t;
        __syncthreads();
    }
    if (i < N2) offs[i] = sh[tid] - v;
    if (tid == 255) bsum[blockIdx.x] = sh[255];
}
__global__ void k_scan2(const int* __restrict__ bsum, int* __restrict__ bscan, int nb) {
    __shared__ int sh[512];
    int tid = threadIdx.x;
    int v = (tid < nb) ? bsum[tid] : 0;
    sh[tid] = v;
    __syncthreads();
#pragma unroll
    for (int off = 1; off < 512; off <<= 1) {
        int t = (tid >= off) ? sh[tid - off] : 0;
        __syncthreads();
        sh[tid] += t;
        __syncthreads();
    }
    if (tid < nb) bscan[tid] = sh[tid] - v;
}
__global__ void k_scan3(int* __restrict__ offs, int* __restrict__ cursor,
                        const int* __restrict__ bscan, int N2, int E2) {
    int i = blockIdx.x * blockDim.x + threadIdx.x;
    if (i < N2) {
        int o = offs[i] + bscan[i >> 8];
        offs[i] = o;
        cursor[i] = o;
    }
    if (i == 0) offs[N2] = E2;
}

__global__ void k_fill2(const int* __restrict__ ei0, const int* __restrict__ ei1,
                        int E, int N, const float* __restrict__ dinv,
                        int* __restrict__ cursor, int* __restrict__ csrc,
                        float* __restrict__ cnorm) {
    int e = blockIdx.x * blockDim.x + threadIdx.x;
    if (e >= 2 * E) return;
    int branch = (e >= E) ? 1 : 0;
    const int* ei = branch ? ei1 : ei0;
    int le = e - branch * E;
    int off = branch * N;
    int s = ei[le] + off;
    int d = ei[E + le] + off;
    int pos = atomicAdd(&cursor[d], 1);
    csrc[pos] = s;
    cnorm[pos] = dinv[s] * dinv[d];
}

// ---------------- GEMM (dual-branch): X@W -> H, optional BN+ReLU on input ------
template <int K, int M, int R, bool BN>
__global__ void k_gemm2(const float* __restrict__ X0, const float* __restrict__ X1,
                        const float* __restrict__ W0, const float* __restrict__ W1,
                        const float* __restrict__ statsBase, int statsStride,
                        float* __restrict__ H, int Nloc, int nbb) {
    constexpr int GROUPS = 128 / M;
    constexpr int RT = R / GROUPS;
    __shared__ float xs[R * K];

    int branch = (blockIdx.x >= nbb) ? 1 : 0;
    int blk = blockIdx.x - branch * nbb;
    int row0 = blk * R;
    const float* X = branch ? X1 : X0;
    const float* W = branch ? W1 : W0;
    const float* st = statsBase + branch * statsStride;

    for (int i = threadIdx.x; i < R * K; i += 128) {
        int r = i / K, k = i - r * K;
        int row = row0 + r;
        float v = (row < Nloc) ? X[(size_t)row * K + k] : 0.f;
        if (BN) v = fmaxf(fmaf(v, st[2 * K + k], st[3 * K + k]), 0.f);
        xs[i] = v;
    }
    __syncthreads();

    int col = threadIdx.x % M;
    int rbase = (threadIdx.x / M) * RT;
    float acc[RT];
#pragma unroll
    for (int r = 0; r < RT; r++) acc[r] = 0.f;

    for (int kc = 0; kc < K; kc += 32) {
        float w[32];
#pragma unroll
        for (int kk = 0; kk < 32; kk++) w[kk] = W[(kc + kk) * M + col];
#pragma unroll
        for (int r = 0; r < RT; r++) {
            const float4* xr = (const float4*)(xs + (rbase + r) * K + kc);
#pragma unroll
            for (int q = 0; q < 8; q++) {
                float4 xv = xr[q];
                acc[r] = fmaf(xv.x, w[4 * q + 0], acc[r]);
                acc[r] = fmaf(xv.y, w[4 * q + 1], acc[r]);
                acc[r] = fmaf(xv.z, w[4 * q + 2], acc[r]);
                acc[r] = fmaf(xv.w, w[4 * q + 3], acc[r]);
            }
        }
    }

    float* Hb = H + (size_t)branch * Nloc * M;
#pragma unroll
    for (int r = 0; r < RT; r++) {
        int row = row0 + rbase + r;
        if (row < Nloc) Hb[(size_t)row * M + col] = acc[r];
    }
}

// ---------------- gather aggregation + fused BN stats ----------------
// grid = 2 * ceil(N/64); block = 256 (8 warps, 8 consecutive nodes per warp)
__global__ void k_agg128s(const int* __restrict__ offs, const int* __restrict__ csrc,
                          const float* __restrict__ cnorm, const float* __restrict__ H,
                          const float* __restrict__ invdeg,
                          const float* __restrict__ b0, const float* __restrict__ b1,
                          float* __restrict__ out, float* __restrict__ stats,
                          int N, int nbb) {
    __shared__ float ssum[128], ssq[128];
    int branch = (blockIdx.x >= nbb) ? 1 : 0;
    int blk = blockIdx.x - branch * nbb;
    int warp = threadIdx.x >> 5, lane = threadIdx.x & 31;
    if (threadIdx.x < 128) { ssum[threadIdx.x] = 0.f; ssq[threadIdx.x] = 0.f; }
    __syncthreads();

    const float* bias = branch ? b1 : b0;
    float4 b = ((const float4*)bias)[lane];
    float4 psum = {0.f, 0.f, 0.f, 0.f}, psq = {0.f, 0.f, 0.f, 0.f};
    int base = blk * 64 + warp * 8;

    for (int i = 0; i < 8; i++) {
        int ln = base + i;
        if (ln >= N) break;
        int node = branch * N + ln;
        float id = invdeg[node];
        float4 acc = ((const float4*)(H + (size_t)node * 128))[lane];
        acc.x = fmaf(acc.x, id, b.x); acc.y = fmaf(acc.y, id, b.y);
        acc.z = fmaf(acc.z, id, b.z); acc.w = fmaf(acc.w, id, b.w);
        int beg = offs[node], end = offs[node + 1];
        for (int j = beg; j < end; j++) {
            int s = __ldg(&csrc[j]);
            float w = __ldg(&cnorm[j]);
            float4 h = ((const float4*)(H + (size_t)s * 128))[lane];
            acc.x = fmaf(h.x, w, acc.x); acc.y = fmaf(h.y, w, acc.y);
            acc.z = fmaf(h.z, w, acc.z); acc.w = fmaf(h.w, w, acc.w);
        }
        ((float4*)(out + (size_t)node * 128))[lane] = acc;
        psum.x += acc.x; psum.y += acc.y; psum.z += acc.z; psum.w += acc.w;
        psq.x = fmaf(acc.x, acc.x, psq.x); psq.y = fmaf(acc.y, acc.y, psq.y);
        psq.z = fmaf(acc.z, acc.z, psq.z); psq.w = fmaf(acc.w, acc.w, psq.w);
    }
    atomicAdd(&ssum[lane * 4 + 0], psum.x); atomicAdd(&ssum[lane * 4 + 1], psum.y);
    atomicAdd(&ssum[lane * 4 + 2], psum.z); atomicAdd(&ssum[lane * 4 + 3], psum.w);
    atomicAdd(&ssq[lane * 4 + 0], psq.x);  atomicAdd(&ssq[lane * 4 + 1], psq.y);
    atomicAdd(&ssq[lane * 4 + 2], psq.z);  atomicAdd(&ssq[lane * 4 + 3], psq.w);
    __syncthreads();
    float* st = stats + branch * 512;
    if (threadIdx.x < 128) atomicAdd(&st[threadIdx.x], ssum[threadIdx.x]);
    else atomicAdd(&st[threadIdx.x], ssq[threadIdx.x - 128]);   // st[128+c]
}

__global__ void k_agg64s(const int* __restrict__ offs, const int* __restrict__ csrc,
                         const float* __restrict__ cnorm, const float* __restrict__ H,
                         const float* __restrict__ invdeg,
                         const float* __restrict__ b0, const float* __restrict__ b1,
                         float* __restrict__ out, float* __restrict__ stats,
                         int N, int nbb) {
    __shared__ float ssum[64], ssq[64];
    int branch = (blockIdx.x >= nbb) ? 1 : 0;
    int blk = blockIdx.x - branch * nbb;
    int warp = threadIdx.x >> 5, lane = threadIdx.x & 31;
    if (threadIdx.x < 64) { ssum[threadIdx.x] = 0.f; ssq[threadIdx.x] = 0.f; }
    __syncthreads();

    const float* bias = branch ? b1 : b0;
    float2 b = ((const float2*)bias)[lane];
    float2 psum = {0.f, 0.f}, psq = {0.f, 0.f};
    int base = blk * 64 + warp * 8;

    for (int i = 0; i < 8; i++) {
        int ln = base + i;
        if (ln >= N) break;
        int node = branch * N + ln;
        float id = invdeg[node];
        float2 acc = ((const float2*)(H + (size_t)node * 64))[lane];
        acc.x = fmaf(acc.x, id, b.x); acc.y = fmaf(acc.y, id, b.y);
        int beg = offs[node], end = offs[node + 1];
        for (int j = beg; j < end; j++) {
            int s = __ldg(&csrc[j]);
            float w = __ldg(&cnorm[j]);
            float2 h = ((const float2*)(H + (size_t)s * 64))[lane];
            acc.x = fmaf(h.x, w, acc.x); acc.y = fmaf(h.y, w, acc.y);
        }
        ((float2*)(out + (size_t)node * 64))[lane] = acc;
        psum.x += acc.x; psum.y += acc.y;
        psq.x = fmaf(acc.x, acc.x, psq.x); psq.y = fmaf(acc.y, acc.y, psq.y);
    }
    atomicAdd(&ssum[lane * 2 + 0], psum.x); atomicAdd(&ssum[lane * 2 + 1], psum.y);
    atomicAdd(&ssq[lane * 2 + 0], psq.x);  atomicAdd(&ssq[lane * 2 + 1], psq.y);
    __syncthreads();
    float* st = stats + branch * 256;
    if (threadIdx.x < 64) atomicAdd(&st[threadIdx.x], ssum[threadIdx.x]);
    else if (threadIdx.x < 128) atomicAdd(&st[threadIdx.x], ssq[threadIdx.x - 64]);
}

// ---------------- BN finalize ----------------
__global__ void k_bnfin(float* __restrict__ stats, int stride,
                        const float* __restrict__ g0, const float* __restrict__ b0,
                        const float* __restrict__ g1, const float* __restrict__ b1,
                        int M, float inv_n) {
    int tid = threadIdx.x;
    int branch = tid / M;
    int c = tid - branch * M;
    const float* g = branch ? g1 : g0;
    const float* be = branch ? b1 : b0;
    float* st = stats + branch * stride;
    float mean = st[c] * inv_n;
    float var = st[M + c] * inv_n - mean * mean;
    float sc = g[c] * rsqrtf(var + 1e-5f);
    st[2 * M + c] = sc;
    st[3 * M + c] = be[c] - mean * sc;
}

// head BN stats (standalone; head output only)
__global__ void k_bnstats(const float* __restrict__ A, float* __restrict__ stats,
                          int Nloc, int M) {
    int c = threadIdx.x;
    int row0 = blockIdx.x * 64;
    int rend = min(row0 + 64, Nloc);
    float s = 0.f, sq = 0.f;
    for (int r = row0; r < rend; r++) {
        float v = A[(size_t)r * M + c];
        s += v;
        sq += v * v;
    }
    atomicAdd(stats + c, s);
    atomicAdd(stats + M + c, sq);
}

// BN+ReLU + mean-pool with run-length-compressed atomics (batch is sorted)
// thread handles one col over 8 consecutive nodes
__global__ void k_bnrelu_pool(const float* __restrict__ A, const float* __restrict__ stats,
                              const int* __restrict__ batch, float* __restrict__ pool,
                              int N, int N2, int G) {
    int t = blockIdx.x * blockDim.x + threadIdx.x;
    int nchunks = (N2 + 7) >> 3;
    int chunk = t >> 6, c = t & 63;
    if (chunk >= nchunks) return;
    int n0 = chunk << 3;
    int nend = min(n0 + 8, N2);
    int curKey = -1;
    float runAcc = 0.f;
    for (int node = n0; node < nend; node++) {
        int branch = (node >= N) ? 1 : 0;
        int ln = node - branch * N;
        const float* st = stats + 1024 + branch * 256;
        float v = fmaxf(fmaf(A[(size_t)node * 64 + c], st[128 + c], st[192 + c]), 0.f);
        int key = branch * G + batch[ln];
        if (key != curKey) {
            if (curKey >= 0) atomicAdd(&pool[(size_t)curKey * 64 + c], runAcc);
            curKey = key;
            runAcc = v;
        } else {
            runAcc += v;
        }
    }
    if (curKey >= 0) atomicAdd(&pool[(size_t)curKey * 64 + c], runAcc);
}

// head GEMM with fused concat+mean: X row g = [pool_c[g]|pool_s[g]] / cnt[g]
__global__ void k_gemmHead(const float* __restrict__ pool, const float* __restrict__ cnt,
                           const float* __restrict__ Wf1, const float* __restrict__ bf1,
                           float* __restrict__ H, int G) {
    constexpr int R = 32;
    __shared__ float xs[R * 128];
    int row0 = blockIdx.x * R;
    for (int i = threadIdx.x; i < R * 128; i += 128) {
        int r = i >> 7, k = i & 127;
        int row = row0 + r;
        float v = 0.f;
        if (row < G) {
            float inv = 1.f / fmaxf(cnt[row], 1.f);
            v = ((k < 64) ? pool[row * 64 + k] : pool[G * 64 + row * 64 + (k - 64)]) * inv;
        }
        xs[i] = v;
    }
    __syncthreads();

    int col = threadIdx.x & 63;
    int rbase = (threadIdx.x >> 6) * 16;
    float bb = bf1[col];
    float acc[16];
#pragma unroll
    for (int r = 0; r < 16; r++) acc[r] = bb;

    for (int kc = 0; kc < 128; kc += 32) {
        float w[32];
#pragma unroll
        for (int kk = 0; kk < 32; kk++) w[kk] = Wf1[(kc + kk) * 64 + col];
#pragma unroll
        for (int r = 0; r < 16; r++) {
            const float4* xr = (const float4*)(xs + (rbase + r) * 128 + kc);
#pragma unroll
            for (int q = 0; q < 8; q++) {
                float4 xv = xr[q];
                acc[r] = fmaf(xv.x, w[4 * q + 0], acc[r]);
                acc[r] = fmaf(xv.y, w[4 * q + 1], acc[r]);
                acc[r] = fmaf(xv.z, w[4 * q + 2], acc[r]);
                acc[r] = fmaf(xv.w, w[4 * q + 3], acc[r]);
            }
        }
    }
#pragma unroll
    for (int r = 0; r < 16; r++) {
        int row = row0 + rbase + r;
        if (row < G) H[(size_t)row * 64 + col] = acc[r];
    }
}

__global__ void k_headout(const float* __restrict__ T, const float* __restrict__ stats,
                          const float* __restrict__ Wf2, const float* __restrict__ bf2,
                          float* __restrict__ out, int G) {
    int g = blockIdx.x * blockDim.x + threadIdx.x;
    if (g >= G) return;
    const float* st = stats + 1536;
    float acc = bf2[0];
    for (int j = 0; j < 64; j++) {
        float v = fmaxf(fmaf(T[g * 64 + j], st[128 + j], st[192 + j]), 0.f);
        acc += v * Wf2[j];
    }
    out[g] = acc;
}

// ---------------- host ----------------
static inline int ceil_div(int a, int b) { return (a + b - 1) / b; }

extern "C" void kernel_launch(void* const* d_in, const int* in_sizes, int n_in,
                              void* d_out, int out_size) {
    const float* xc   = (const float*)d_in[0];
    const float* xs_  = (const float*)d_in[1];
    const int*   eic  = (const int*)d_in[2];
    const int*   eis  = (const int*)d_in[3];
    const int*   batch= (const int*)d_in[4];
    const float* W1c = (const float*)d_in[5],  *b1c = (const float*)d_in[6];
    const float* g1c = (const float*)d_in[7],  *be1c= (const float*)d_in[8];
    const float* W2c = (const float*)d_in[9],  *b2c = (const float*)d_in[10];
    const float* g2c = (const float*)d_in[11], *be2c= (const float*)d_in[12];
    const float* W1s = (const float*)d_in[13], *b1s = (const float*)d_in[14];
    const float* g1s = (const float*)d_in[15], *be1s= (const float*)d_in[16];
    const float* W2s = (const float*)d_in[17], *b2s = (const float*)d_in[18];
    const float* g2s = (const float*)d_in[19], *be2s= (const float*)d_in[20];
    const float* Wf1 = (const float*)d_in[21], *bf1 = (const float*)d_in[22];
    const float* gf1 = (const float*)d_in[23], *bef1= (const float*)d_in[24];
    const float* Wf2 = (const float*)d_in[25], *bf2 = (const float*)d_in[26];

    const int N = in_sizes[0] / 64;
    const int E = in_sizes[2] / 2;
    const int G = out_size;
    const int N2 = 2 * N;
    const int E2 = 2 * E;

    float *bufA, *bufB, *dinv, *invdeg, *stats, *pool, *cnt, *headT, *cnorm;
    int *deg, *offs, *cursor, *bsum, *bscan, *csrc;
    cudaGetSymbolAddress((void**)&bufA, g_bufA);
    cudaGetSymbolAddress((void**)&bufB, g_bufB);
    cudaGetSymbolAddress((void**)&deg, g_deg);
    cudaGetSymbolAddress((void**)&dinv, g_dinv);
    cudaGetSymbolAddress((void**)&invdeg, g_invdeg);
    cudaGetSymbolAddress((void**)&offs, g_offs);
    cudaGetSymbolAddress((void**)&cursor, g_cursor);
    cudaGetSymbolAddress((void**)&bsum, g_bsum);
    cudaGetSymbolAddress((void**)&bscan, g_bscan);
    cudaGetSymbolAddress((void**)&csrc, g_csrc);
    cudaGetSymbolAddress((void**)&cnorm, g_cnorm);
    cudaGetSymbolAddress((void**)&stats, g_stats);
    cudaGetSymbolAddress((void**)&pool, g_pool);
    cudaGetSymbolAddress((void**)&cnt, g_cnt);
    cudaGetSymbolAddress((void**)&headT, g_headT);

    const int nbScan = ceil_div(N2, 256);
    const int zeroTotal = N2 + 2048 + 2 * G * 64 + G;

    k_zero_all<<<ceil_div(zeroTotal, 256), 256>>>(deg, N2, stats, 2048,
                                                  pool, 2 * G * 64, cnt, G);
    k_hist<<<ceil_div(N + E2, 256), 256>>>(batch, N, eic, eis, E, cnt, deg);
    k_scan1<<<nbScan, 256>>>(deg, offs, bsum, dinv, invdeg, N2);
    k_scan2<<<1, 512>>>(bsum, bscan, nbScan);
    k_scan3<<<ceil_div(N2, 256), 256>>>(offs, cursor, bscan, N2, E2);
    k_fill2<<<ceil_div(E2, 256), 256>>>(eic, eis, E, N, dinv, cursor, csrc, cnorm);

    const int nbbL1 = ceil_div(N, 16);   // GEMM1 R=16, M=128
    const int nbbL2 = ceil_div(N, 32);   // GEMM2 R=32, M=64
    const int nbbAg = ceil_div(N, 64);   // agg+stats: 64 nodes/block

    // ---- layer 1: 64 -> 128 ----
    k_gemm2<64, 128, 16, false><<<2 * nbbL1, 128>>>(xc, xs_, W1c, W1s,
                                                    stats, 0, bufB, N, nbbL1);
    k_agg128s<<<2 * nbbAg, 256>>>(offs, csrc, cnorm, bufB, invdeg, b1c, b1s,
                                  bufA, stats, N, nbbAg);
    k_bnfin<<<1, 256>>>(stats, 512, g1c, be1c, g1s, be1s, 128, 1.f / (float)N);

    // ---- layer 2: 128 -> 64 (BN+ReLU fused into GEMM input) ----
    k_gemm2<128, 64, 32, true><<<2 * nbbL2, 128>>>(bufA, bufA + (size_t)N * 128, W2c, W2s,
                                                   stats, 512, bufB, N, nbbL2);
    k_agg64s<<<2 * nbbAg, 256>>>(offs, csrc, cnorm, bufB, invdeg, b2c, b2s,
                                 bufA, stats + 1024, N, nbbAg);
    k_bnfin<<<1, 128>>>(stats + 1024, 256, g2c, be2c, g2s, be2s, 64, 1.f / (float)N);

    // ---- BN+ReLU + mean pool (run-length atomics) ----
    k_bnrelu_pool<<<ceil_div(ceil_div(N2, 8) * 64, 256), 256>>>(bufA, stats, batch,
                                                                pool, N, N2, G);

    // ---- head (concat+mean fused into GEMM loader) ----
    k_gemmHead<<<ceil_div(G, 32), 128>>>(pool, cnt, Wf1, bf1, headT, G);
    k_bnstats<<<ceil_div(G, 64), 64>>>(headT, stats + 1536, G, 64);
    k_bnfin<<<1, 64>>>(stats + 1536, 0, gf1, bef1, gf1, bef1, 64, 1.f / (float)G);
    k_headout<<<ceil_div(G, 256), 256>>>(headT, stats, Wf2, bf2, (float*)d_out, G);
}

// round 7
// speedup vs baseline: 1.0744x; 1.0744x over previous
#include <cuda_runtime.h>

// ---------------- scratch (no allocation allowed) ----------------
#define N2MAX  100096
#define E2MAX  1200128
#define GMAX   2048

__device__ float g_bufA[N2MAX * 128];
__device__ float g_bufB[N2MAX * 128];
__device__ int   g_deg[N2MAX];
__device__ float g_dinv[N2MAX];
__device__ float g_invdeg[N2MAX];
__device__ int   g_offs[N2MAX + 1];
__device__ int   g_cursor[N2MAX];
__device__ int   g_bsum[512];
__device__ int   g_bscan[512];
__device__ int   g_csrc[E2MAX];
__device__ float g_cnorm[E2MAX];
// stats layout:
//  L1: branch b at b*512 {sum128, sumsq128, scale128, shift128}
//  L2: branch b at 1024 + b*256 {sum64, sumsq64, scale64, shift64}
//  head: 1536 {sum64, sumsq64, scale64, shift64}
__device__ float g_stats[2048];
__device__ float g_pool[2 * GMAX * 64];
__device__ float g_cnt[GMAX];
__device__ float g_headT[GMAX * 64];

// ---------------- init ----------------
__global__ void k_zero_all(int* deg, int nd, float* stats, int ns,
                           float* pool, int np, float* cnt, int nc) {
    int i = blockIdx.x * blockDim.x + threadIdx.x;
    if (i < nd) { deg[i] = 0; return; }
    i -= nd;
    if (i < ns) { stats[i] = 0.f; return; }
    i -= ns;
    if (i < np) { pool[i] = 0.f; return; }
    i -= np;
    if (i < nc) cnt[i] = 0.f;
}

// combined: graph-size histogram (first N threads) + in-degree histogram (next 2E)
__global__ void k_hist(const int* __restrict__ batch, int N,
                       const int* __restrict__ ei0, const int* __restrict__ ei1,
                       int E, float* __restrict__ cnt, int* __restrict__ deg) {
    int i = blockIdx.x * blockDim.x + threadIdx.x;
    if (i < N) { atomicAdd(&cnt[batch[i]], 1.f); return; }
    int e = i - N;
    if (e >= 2 * E) return;
    int d = (e < E) ? ei0[E + e] : (ei1[E + (e - E)] + N);
    atomicAdd(&deg[d], 1);
}

// ---------------- scan phase 1 (+degree finalize fused) ----------------
__global__ void k_scan1(const int* __restrict__ deg, int* __restrict__ offs,
                        int* __restrict__ bsum, float* __restrict__ dinv,
                        float* __restrict__ invdeg, int N2) {
    __shared__ int sh[256];
    int tid = threadIdx.x;
    int i = blockIdx.x * 256 + tid;
    int v = (i < N2) ? deg[i] : 0;
    if (i < N2) {
        float d = (float)v + 1.f;
        dinv[i] = rsqrtf(d);
        invdeg[i] = 1.f / d;
    }
    sh[tid] = v;
    __syncthreads();
#pragma unroll
    for (int off = 1; off < 256; off <<= 1) {
        int t = (tid >= off) ? sh[tid - off] : 0;
        __syncthreads();
        sh[tid] += t;
        __syncthreads();
    }
    if (i < N2) offs[i] = sh[tid] - v;
    if (tid == 255) bsum[blockIdx.x] = sh[255];
}
__global__ void k_scan2(const int* __restrict__ bsum, int* __restrict__ bscan, int nb) {
    __shared__ int sh[512];
    int tid = threadIdx.x;
    int v = (tid < nb) ? bsum[tid] : 0;
    sh[tid] = v;
    __syncthreads();
#pragma unroll
    for (int off = 1; off < 512; off <<= 1) {
        int t = (tid >= off) ? sh[tid - off] : 0;
        __syncthreads();
        sh[tid] += t;
        __syncthreads();
    }
    if (tid < nb) bscan[tid] = sh[tid] - v;
}
__global__ void k_scan3(int* __restrict__ offs, int* __restrict__ cursor,
                        const int* __restrict__ bscan, int N2, int E2) {
    int i = blockIdx.x * blockDim.x + threadIdx.x;
    if (i < N2) {
        int o = offs[i] + bscan[i >> 8];
        offs[i] = o;
        cursor[i] = o;
    }
    if (i == 0) offs[N2] = E2;
}

__global__ void k_fill2(const int* __restrict__ ei0, const int* __restrict__ ei1,
                        int E, int N, const float* __restrict__ dinv,
                        int* __restrict__ cursor, int* __restrict__ csrc,
                        float* __restrict__ cnorm) {
    int e = blockIdx.x * blockDim.x + threadIdx.x;
    if (e >= 2 * E) return;
    int branch = (e >= E) ? 1 : 0;
    const int* ei = branch ? ei1 : ei0;
    int le = e - branch * E;
    int off = branch * N;
    int s = ei[le] + off;
    int d = ei[E + le] + off;
    int pos = atomicAdd(&cursor[d], 1);
    csrc[pos] = s;
    cnorm[pos] = dinv[s] * dinv[d];
}

// ---------------- GEMM (dual-branch): X@W -> H, optional BN+ReLU on input ------
// blockDim = 128. col = tid % M, RT rows per thread, W cached in 32-reg chunks.
template <int K, int M, int R, bool BN>
__global__ void k_gemm2(const float* __restrict__ X0, const float* __restrict__ X1,
                        const float* __restrict__ W0, const float* __restrict__ W1,
                        const float* __restrict__ statsBase, int statsStride,
                        float* __restrict__ H, int Nloc, int nbb) {
    constexpr int GROUPS = 128 / M;
    constexpr int RT = R / GROUPS;
    __shared__ float xs[R * K];

    int branch = (blockIdx.x >= nbb) ? 1 : 0;
    int blk = blockIdx.x - branch * nbb;
    int row0 = blk * R;
    const float* X = branch ? X1 : X0;
    const float* W = branch ? W1 : W0;
    const float* st = statsBase + branch * statsStride;

    for (int i = threadIdx.x; i < R * K; i += 128) {
        int r = i / K, k = i - r * K;
        int row = row0 + r;
        float v = (row < Nloc) ? X[(size_t)row * K + k] : 0.f;
        if (BN) v = fmaxf(fmaf(v, st[2 * K + k], st[3 * K + k]), 0.f);
        xs[i] = v;
    }
    __syncthreads();

    int col = threadIdx.x % M;
    int rbase = (threadIdx.x / M) * RT;
    float acc[RT];
#pragma unroll
    for (int r = 0; r < RT; r++) acc[r] = 0.f;

    for (int kc = 0; kc < K; kc += 32) {
        float w[32];
#pragma unroll
        for (int kk = 0; kk < 32; kk++) w[kk] = W[(kc + kk) * M + col];
#pragma unroll
        for (int r = 0; r < RT; r++) {
            const float4* xr = (const float4*)(xs + (rbase + r) * K + kc);
#pragma unroll
            for (int q = 0; q < 8; q++) {
                float4 xv = xr[q];
                acc[r] = fmaf(xv.x, w[4 * q + 0], acc[r]);
                acc[r] = fmaf(xv.y, w[4 * q + 1], acc[r]);
                acc[r] = fmaf(xv.z, w[4 * q + 2], acc[r]);
                acc[r] = fmaf(xv.w, w[4 * q + 3], acc[r]);
            }
        }
    }

    float* Hb = H + (size_t)branch * Nloc * M;
#pragma unroll
    for (int r = 0; r < RT; r++) {
        int row = row0 + rbase + r;
        if (row < Nloc) Hb[(size_t)row * M + col] = acc[r];
    }
}

// ---------------- gather aggregation: 1 warp per node ----------------
__global__ void k_agg128(const int* __restrict__ offs, const int* __restrict__ csrc,
                         const float* __restrict__ cnorm, const float* __restrict__ H,
                         const float* __restrict__ invdeg,
                         const float* __restrict__ b0, const float* __restrict__ b1,
                         float* __restrict__ out, int N, int N2) {
    int node = blockIdx.x * (blockDim.x >> 5) + (threadIdx.x >> 5);
    int lane = threadIdx.x & 31;
    if (node >= N2) return;
    const float* bias = (node >= N) ? b1 : b0;
    float id = invdeg[node];
    float4 acc = *(const float4*)(H + (size_t)node * 128 + lane * 4);
    float4 b = *(const float4*)(bias + lane * 4);
    acc.x = fmaf(acc.x, id, b.x); acc.y = fmaf(acc.y, id, b.y);
    acc.z = fmaf(acc.z, id, b.z); acc.w = fmaf(acc.w, id, b.w);
    int beg = offs[node], end = offs[node + 1];
    for (int j = beg; j < end; j++) {
        int s = __ldg(&csrc[j]);
        float w = __ldg(&cnorm[j]);
        float4 h = *(const float4*)(H + (size_t)s * 128 + lane * 4);
        acc.x = fmaf(h.x, w, acc.x); acc.y = fmaf(h.y, w, acc.y);
        acc.z = fmaf(h.z, w, acc.z); acc.w = fmaf(h.w, w, acc.w);
    }
    *(float4*)(out + (size_t)node * 128 + lane * 4) = acc;
}
__global__ void k_agg64(const int* __restrict__ offs, const int* __restrict__ csrc,
                        const float* __restrict__ cnorm, const float* __restrict__ H,
                        const float* __restrict__ invdeg,
                        const float* __restrict__ b0, const float* __restrict__ b1,
                        float* __restrict__ out, int N, int N2) {
    int node = blockIdx.x * (blockDim.x >> 5) + (threadIdx.x >> 5);
    int lane = threadIdx.x & 31;
    if (node >= N2) return;
    const float* bias = (node >= N) ? b1 : b0;
    float id = invdeg[node];
    float2 acc = *(const float2*)(H + (size_t)node * 64 + lane * 2);
    float2 b = *(const float2*)(bias + lane * 2);
    acc.x = fmaf(acc.x, id, b.x); acc.y = fmaf(acc.y, id, b.y);
    int beg = offs[node], end = offs[node + 1];
    for (int j = beg; j < end; j++) {
        int s = __ldg(&csrc[j]);
        float w = __ldg(&cnorm[j]);
        float2 h = *(const float2*)(H + (size_t)s * 64 + lane * 2);
        acc.x = fmaf(h.x, w, acc.x); acc.y = fmaf(h.y, w, acc.y);
    }
    *(float2*)(out + (size_t)node * 64 + lane * 2) = acc;
}

// ---------------- BN ----------------
__global__ void k_bnstats(const float* __restrict__ A, float* __restrict__ stats,
                          int stride, int nbb, int Nloc, int M) {
    int branch = (blockIdx.x >= nbb) ? 1 : 0;
    int blk = blockIdx.x - branch * nbb;
    int c = threadIdx.x;
    int row0 = blk * 64;
    int rend = min(row0 + 64, Nloc);
    const float* Ab = A + (size_t)branch * Nloc * M;
    float* st = stats + branch * stride;
    float s = 0.f, sq = 0.f;
    for (int r = row0; r < rend; r++) {
        float v = Ab[(size_t)r * M + c];
        s += v;
        sq += v * v;
    }
    atomicAdd(st + c, s);
    atomicAdd(st + M + c, sq);
}
__global__ void k_bnfin(float* __restrict__ stats, int stride,
                        const float* __restrict__ g0, const float* __restrict__ b0,
                        const float* __restrict__ g1, const float* __restrict__ b1,
                        int M, float inv_n) {
    int tid = threadIdx.x;
    int branch = tid / M;
    int c = tid - branch * M;
    const float* g = branch ? g1 : g0;
    const float* be = branch ? b1 : b0;
    float* st = stats + branch * stride;
    float mean = st[c] * inv_n;
    float var = st[M + c] * inv_n - mean * mean;
    float sc = g[c] * rsqrtf(var + 1e-5f);
    st[2 * M + c] = sc;
    st[3 * M + c] = be[c] - mean * sc;
}

__global__ void k_bnrelu_pool(const float* __restrict__ A, const float* __restrict__ stats,
                              const int* __restrict__ batch, float* __restrict__ pool,
                              int N, int N2, int G) {
    int idx = blockIdx.x * blockDim.x + threadIdx.x;
    if (idx >= N2 * 64) return;
    int node = idx >> 6, c = idx & 63;
    int branch = (node >= N) ? 1 : 0;
    int ln = node - branch * N;
    const float* st = stats + 1024 + branch * 256;
    float v = fmaxf(fmaf(A[idx], st[128 + c], st[192 + c]), 0.f);
    atomicAdd(&pool[branch * G * 64 + batch[ln] * 64 + c], v);
}

// head GEMM with fused concat+mean: X row g = [pool_c[g]|pool_s[g]] / cnt[g]
__global__ void k_gemmHead(const float* __restrict__ pool, const float* __restrict__ cnt,
                           const float* __restrict__ Wf1, const float* __restrict__ bf1,
                           float* __restrict__ H, int G) {
    constexpr int R = 32;
    __shared__ float xs[R * 128];
    int row0 = blockIdx.x * R;
    for (int i = threadIdx.x; i < R * 128; i += 128) {
        int r = i >> 7, k = i & 127;
        int row = row0 + r;
        float v = 0.f;
        if (row < G) {
            float inv = 1.f / fmaxf(cnt[row], 1.f);
            v = ((k < 64) ? pool[row * 64 + k] : pool[G * 64 + row * 64 + (k - 64)]) * inv;
        }
        xs[i] = v;
    }
    __syncthreads();

    int col = threadIdx.x & 63;
    int rbase = (threadIdx.x >> 6) * 16;
    float bb = bf1[col];
    float acc[16];
#pragma unroll
    for (int r = 0; r < 16; r++) acc[r] = bb;

    for (int kc = 0; kc < 128; kc += 32) {
        float w[32];
#pragma unroll
        for (int kk = 0; kk < 32; kk++) w[kk] = Wf1[(kc + kk) * 64 + col];
#pragma unroll
        for (int r = 0; r < 16; r++) {
            const float4* xr = (const float4*)(xs + (rbase + r) * 128 + kc);
#pragma unroll
            for (int q = 0; q < 8; q++) {
                float4 xv = xr[q];
                acc[r] = fmaf(xv.x, w[4 * q + 0], acc[r]);
                acc[r] = fmaf(xv.y, w[4 * q + 1], acc[r]);
                acc[r] = fmaf(xv.z, w[4 * q + 2], acc[r]);
                acc[r] = fmaf(xv.w, w[4 * q + 3], acc[r]);
            }
        }
    }
#pragma unroll
    for (int r = 0; r < 16; r++) {
        int row = row0 + rbase + r;
        if (row < G) H[(size_t)row * 64 + col] = acc[r];
    }
}

__global__ void k_headout(const float* __restrict__ T, const float* __restrict__ stats,
                          const float* __restrict__ Wf2, const float* __restrict__ bf2,
                          float* __restrict__ out, int G) {
    int g = blockIdx.x * blockDim.x + threadIdx.x;
    if (g >= G) return;
    const float* st = stats + 1536;
    float acc = bf2[0];
    for (int j = 0; j < 64; j++) {
        float v = fmaxf(fmaf(T[g * 64 + j], st[128 + j], st[192 + j]), 0.f);
        acc += v * Wf2[j];
    }
    out[g] = acc;
}

// ---------------- host ----------------
static inline int ceil_div(int a, int b) { return (a + b - 1) / b; }

extern "C" void kernel_launch(void* const* d_in, const int* in_sizes, int n_in,
                              void* d_out, int out_size) {
    const float* xc   = (const float*)d_in[0];
    const float* xs_  = (const float*)d_in[1];
    const int*   eic  = (const int*)d_in[2];
    const int*   eis  = (const int*)d_in[3];
    const int*   batch= (const int*)d_in[4];
    const float* W1c = (const float*)d_in[5],  *b1c = (const float*)d_in[6];
    const float* g1c = (const float*)d_in[7],  *be1c= (const float*)d_in[8];
    const float* W2c = (const float*)d_in[9],  *b2c = (const float*)d_in[10];
    const float* g2c = (const float*)d_in[11], *be2c= (const float*)d_in[12];
    const float* W1s = (const float*)d_in[13], *b1s = (const float*)d_in[14];
    const float* g1s = (const float*)d_in[15], *be1s= (const float*)d_in[16];
    const float* W2s = (const float*)d_in[17], *b2s = (const float*)d_in[18];
    const float* g2s = (const float*)d_in[19], *be2s= (const float*)d_in[20];
    const float* Wf1 = (const float*)d_in[21], *bf1 = (const float*)d_in[22];
    const float* gf1 = (const float*)d_in[23], *bef1= (const float*)d_in[24];
    const float* Wf2 = (const float*)d_in[25], *bf2 = (const float*)d_in[26];

    const int N = in_sizes[0] / 64;
    const int E = in_sizes[2] / 2;
    const int G = out_size;
    const int N2 = 2 * N;
    const int E2 = 2 * E;

    float *bufA, *bufB, *dinv, *invdeg, *stats, *pool, *cnt, *headT, *cnorm;
    int *deg, *offs, *cursor, *bsum, *bscan, *csrc;
    cudaGetSymbolAddress((void**)&bufA, g_bufA);
    cudaGetSymbolAddress((void**)&bufB, g_bufB);
    cudaGetSymbolAddress((void**)&deg, g_deg);
    cudaGetSymbolAddress((void**)&dinv, g_dinv);
    cudaGetSymbolAddress((void**)&invdeg, g_invdeg);
    cudaGetSymbolAddress((void**)&offs, g_offs);
    cudaGetSymbolAddress((void**)&cursor, g_cursor);
    cudaGetSymbolAddress((void**)&bsum, g_bsum);
    cudaGetSymbolAddress((void**)&bscan, g_bscan);
    cudaGetSymbolAddress((void**)&csrc, g_csrc);
    cudaGetSymbolAddress((void**)&cnorm, g_cnorm);
    cudaGetSymbolAddress((void**)&stats, g_stats);
    cudaGetSymbolAddress((void**)&pool, g_pool);
    cudaGetSymbolAddress((void**)&cnt, g_cnt);
    cudaGetSymbolAddress((void**)&headT, g_headT);

    const int nbScan = ceil_div(N2, 256);
    const int zeroTotal = N2 + 2048 + 2 * G * 64 + G;

    k_zero_all<<<ceil_div(zeroTotal, 256), 256>>>(deg, N2, stats, 2048,
                                                  pool, 2 * G * 64, cnt, G);
    k_hist<<<ceil_div(N + E2, 256), 256>>>(batch, N, eic, eis, E, cnt, deg);
    k_scan1<<<nbScan, 256>>>(deg, offs, bsum, dinv, invdeg, N2);
    k_scan2<<<1, 512>>>(bsum, bscan, nbScan);
    k_scan3<<<ceil_div(N2, 256), 256>>>(offs, cursor, bscan, N2, E2);
    k_fill2<<<ceil_div(E2, 256), 256>>>(eic, eis, E, N, dinv, cursor, csrc, cnorm);

    const int nbbL1 = ceil_div(N, 16);   // GEMM1 R=16, M=128
    const int nbbL2 = ceil_div(N, 32);   // GEMM2 R=32, M=64
    const int nbbBN = ceil_div(N, 64);

    // ---- layer 1: 64 -> 128 ----
    k_gemm2<64, 128, 16, false><<<2 * nbbL1, 128>>>(xc, xs_, W1c, W1s,
                                                    stats, 0, bufB, N, nbbL1);
    k_agg128<<<ceil_div(N2, 8), 256>>>(offs, csrc, cnorm, bufB, invdeg, b1c, b1s, bufA, N, N2);
    k_bnstats<<<2 * nbbBN, 128>>>(bufA, stats, 512, nbbBN, N, 128);
    k_bnfin<<<1, 256>>>(stats, 512, g1c, be1c, g1s, be1s, 128, 1.f / (float)N);

    // ---- layer 2: 128 -> 64 (BN+ReLU fused into GEMM input) ----
    k_gemm2<128, 64, 32, true><<<2 * nbbL2, 128>>>(bufA, bufA + (size_t)N * 128, W2c, W2s,
                                                   stats, 512, bufB, N, nbbL2);
    k_agg64<<<ceil_div(N2, 8), 256>>>(offs, csrc, cnorm, bufB, invdeg, b2c, b2s, bufA, N, N2);
    k_bnstats<<<2 * nbbBN, 64>>>(bufA, stats + 1024, 256, nbbBN, N, 64);
    k_bnfin<<<1, 128>>>(stats + 1024, 256, g2c, be2c, g2s, be2s, 64, 1.f / (float)N);

    // ---- BN+ReLU + mean pool ----
    k_bnrelu_pool<<<ceil_div(N2 * 64, 256), 256>>>(bufA, stats, batch, pool, N, N2, G);

    // ---- head (concat+mean fused into GEMM loader) ----
    k_gemmHead<<<ceil_div(G, 32), 128>>>(pool, cnt, Wf1, bf1, headT, G);
    const int nbbHS = ceil_div(G, 64);
    k_bnstats<<<nbbHS, 64>>>(headT, stats + 1536, 0, nbbHS, G, 64);
    k_bnfin<<<1, 64>>>(stats + 1536, 0, gf1, bef1, gf1, bef1, 64, 1.f / (float)G);
    k_headout<<<ceil_div(G, 256), 256>>>(headT, stats, Wf2, bf2, (float*)d_out, G);
}

// round 11
// speedup vs baseline: 1.1005x; 1.0243x over previous
#include <cuda_runtime.h>

// ---------------- scratch (no allocation allowed) ----------------
#define N2MAX  100096
#define E2MAX  1200128
#define GMAX   2048

__device__ float g_bufA[N2MAX * 128];
__device__ float g_bufB[N2MAX * 128];
__device__ int   g_deg[N2MAX];
__device__ float g_dinv[N2MAX];
__device__ float g_invdeg[N2MAX];
__device__ int   g_offs[N2MAX + 1];
__device__ int   g_cursor[N2MAX];
__device__ int   g_bsum[512];
__device__ int   g_bscan[512];
__device__ int   g_csrc[E2MAX];
__device__ float g_cnorm[E2MAX];
// stats layout (raw sums only; scale/shift computed by consumers):
//  L1: branch b at b*512      {sum128, sumsq128}
//  L2: branch b at 1024+b*256 {sum64, sumsq64}
//  head: 1536                 {sum64, sumsq64}
__device__ float g_stats[2048];
__device__ float g_pool[2 * GMAX * 64];
__device__ float g_cnt[GMAX];
__device__ float g_headT[GMAX * 64];

// ---------------- stream fork/join resources (static init, pre-checkpoint) ----
struct HxStreams {
    cudaStream_t s2 = nullptr;
    cudaEvent_t evFork = nullptr, evJoin = nullptr;
    bool ok = false;
    HxStreams() {
        ok = (cudaStreamCreateWithFlags(&s2, cudaStreamNonBlocking) == cudaSuccess) &&
             (cudaEventCreateWithFlags(&evFork, cudaEventDisableTiming) == cudaSuccess) &&
             (cudaEventCreateWithFlags(&evJoin, cudaEventDisableTiming) == cudaSuccess);
    }
};
static HxStreams g_hx;

// ---------------- init ----------------
__global__ void k_zero_all(int* deg, int nd, float* stats, int ns,
                           float* pool, int np, float* cnt, int nc) {
    int i = blockIdx.x * blockDim.x + threadIdx.x;
    if (i < nd) { deg[i] = 0; return; }
    i -= nd;
    if (i < ns) { stats[i] = 0.f; return; }
    i -= ns;
    if (i < np) { pool[i] = 0.f; return; }
    i -= np;
    if (i < nc) cnt[i] = 0.f;
}

// combined: graph-size histogram (first N threads) + in-degree histogram (next 2E)
__global__ void k_hist(const int* __restrict__ batch, int N,
                       const int* __restrict__ ei0, const int* __restrict__ ei1,
                       int E, float* __restrict__ cnt, int* __restrict__ deg) {
    int i = blockIdx.x * blockDim.x + threadIdx.x;
    if (i < N) { atomicAdd(&cnt[batch[i]], 1.f); return; }
    int e = i - N;
    if (e >= 2 * E) return;
    int d = (e < E) ? ei0[E + e] : (ei1[E + (e - E)] + N);
    atomicAdd(&deg[d], 1);
}

// ---------------- scan phase 1 (+degree finalize fused) ----------------
__global__ void k_scan1(const int* __restrict__ deg, int* __restrict__ offs,
                        int* __restrict__ bsum, float* __restrict__ dinv,
                        float* __restrict__ invdeg, int N2) {
    __shared__ int sh[256];
    int tid = threadIdx.x;
    int i = blockIdx.x * 256 + tid;
    int v = (i < N2) ? deg[i] : 0;
    if (i < N2) {
        float d = (float)v + 1.f;
        dinv[i] = rsqrtf(d);
        invdeg[i] = 1.f / d;
    }
    sh[tid] = v;
    __syncthreads();
#pragma unroll
    for (int off = 1; off < 256; off <<= 1) {
        int t = (tid >= off) ? sh[tid - off] : 0;
        __syncthreads();
        sh[tid] += t;
        __syncthreads();
    }
    if (i < N2) offs[i] = sh[tid] - v;
    if (tid == 255) bsum[blockIdx.x] = sh[255];
}
__global__ void k_scan2(const int* __restrict__ bsum, int* __restrict__ bscan, int nb) {
    __shared__ int sh[512];
    int tid = threadIdx.x;
    int v = (tid < nb) ? bsum[tid] : 0;
    sh[tid] = v;
    __syncthreads();
#pragma unroll
    for (int off = 1; off < 512; off <<= 1) {
        int t = (tid >= off) ? sh[tid - off] : 0;
        __syncthreads();
        sh[tid] += t;
        __syncthreads();
    }
    if (tid < nb) bscan[tid] = sh[tid] - v;
}
__global__ void k_scan3(int* __restrict__ offs, int* __restrict__ cursor,
                        const int* __restrict__ bscan, int N2, int E2) {
    int i = blockIdx.x * blockDim.x + threadIdx.x;
    if (i < N2) {
        int o = offs[i] + bscan[i >> 8];
        offs[i] = o;
        cursor[i] = o;
    }
    if (i == 0) offs[N2] = E2;
}

__global__ void k_fill2(const int* __restrict__ ei0, const int* __restrict__ ei1,
                        int E, int N, const float* __restrict__ dinv,
                        int* __restrict__ cursor, int* __restrict__ csrc,
                        float* __restrict__ cnorm) {
    int e = blockIdx.x * blockDim.x + threadIdx.x;
    if (e >= 2 * E) return;
    int branch = (e >= E) ? 1 : 0;
    const int* ei = branch ? ei1 : ei0;
    int le = e - branch * E;
    int off = branch * N;
    int s = ei[le] + off;
    int d = ei[E + le] + off;
    int pos = atomicAdd(&cursor[d], 1);
    csrc[pos] = s;
    cnorm[pos] = dinv[s] * dinv[d];
}

// ---------------- GEMM (dual-branch): X@W -> H, optional BN+ReLU on input ------
// blockDim = 128. col = tid % M, RT rows per thread, W cached in 32-reg chunks.
// BN path computes scale/shift from raw sums (statsBase) + gamma/beta in smem.
template <int K, int M, int R, bool BN>
__global__ void k_gemm2(const float* __restrict__ X0, const float* __restrict__ X1,
                        const float* __restrict__ W0, const float* __restrict__ W1,
                        const float* __restrict__ statsBase, int statsStride,
                        const float* __restrict__ ga0, const float* __restrict__ be0,
                        const float* __restrict__ ga1, const float* __restrict__ be1,
                        float inv_n,
                        float* __restrict__ H, int Nloc, int nbb) {
    constexpr int GROUPS = 128 / M;
    constexpr int RT = R / GROUPS;
    __shared__ float xs[R * K];
    __shared__ float scs[K], shs[K];

    int branch = (blockIdx.x >= nbb) ? 1 : 0;
    int blk = blockIdx.x - branch * nbb;
    int row0 = blk * R;
    const float* X = branch ? X1 : X0;
    const float* W = branch ? W1 : W0;

    if (BN) {
        if (threadIdx.x < K) {
            const float* st = statsBase + branch * statsStride;
            const float* ga = branch ? ga1 : ga0;
            const float* be = branch ? be1 : be0;
            int c = threadIdx.x;
            float mean = st[c] * inv_n;
            float var = st[K + c] * inv_n - mean * mean;
            float s = ga[c] * rsqrtf(var + 1e-5f);
            scs[c] = s;
            shs[c] = be[c] - mean * s;
        }
        __syncthreads();
    }

    for (int i = threadIdx.x; i < R * K; i += 128) {
        int r = i / K, k = i - r * K;
        int row = row0 + r;
        float v = (row < Nloc) ? X[(size_t)row * K + k] : 0.f;
        if (BN) v = fmaxf(fmaf(v, scs[k], shs[k]), 0.f);
        xs[i] = v;
    }
    __syncthreads();

    int col = threadIdx.x % M;
    int rbase = (threadIdx.x / M) * RT;
    float acc[RT];
#pragma unroll
    for (int r = 0; r < RT; r++) acc[r] = 0.f;

    for (int kc = 0; kc < K; kc += 32) {
        float w[32];
#pragma unroll
        for (int kk = 0; kk < 32; kk++) w[kk] = W[(kc + kk) * M + col];
#pragma unroll
        for (int r = 0; r < RT; r++) {
            const float4* xr = (const float4*)(xs + (rbase + r) * K + kc);
#pragma unroll
            for (int q = 0; q < 8; q++) {
                float4 xv = xr[q];
                acc[r] = fmaf(xv.x, w[4 * q + 0], acc[r]);
                acc[r] = fmaf(xv.y, w[4 * q + 1], acc[r]);
                acc[r] = fmaf(xv.z, w[4 * q + 2], acc[r]);
                acc[r] = fmaf(xv.w, w[4 * q + 3], acc[r]);
            }
        }
    }

    float* Hb = H + (size_t)branch * Nloc * M;
#pragma unroll
    for (int r = 0; r < RT; r++) {
        int row = row0 + rbase + r;
        if (row < Nloc) Hb[(size_t)row * M + col] = acc[r];
    }
}

// ---------------- gather aggregation: 1 warp per node ----------------
__global__ void k_agg128(const int* __restrict__ offs, const int* __restrict__ csrc,
                         const float* __restrict__ cnorm, const float* __restrict__ H,
                         const float* __restrict__ invdeg,
                         const float* __restrict__ b0, const float* __restrict__ b1,
                         float* __restrict__ out, int N, int N2) {
    int node = blockIdx.x * (blockDim.x >> 5) + (threadIdx.x >> 5);
    int lane = threadIdx.x & 31;
    if (node >= N2) return;
    const float* bias = (node >= N) ? b1 : b0;
    float id = invdeg[node];
    float4 acc = *(const float4*)(H + (size_t)node * 128 + lane * 4);
    float4 b = *(const float4*)(bias + lane * 4);
    acc.x = fmaf(acc.x, id, b.x); acc.y = fmaf(acc.y, id, b.y);
    acc.z = fmaf(acc.z, id, b.z); acc.w = fmaf(acc.w, id, b.w);
    int beg = offs[node], end = offs[node + 1];
    for (int j = beg; j < end; j++) {
        int s = __ldg(&csrc[j]);
        float w = __ldg(&cnorm[j]);
        float4 h = *(const float4*)(H + (size_t)s * 128 + lane * 4);
        acc.x = fmaf(h.x, w, acc.x); acc.y = fmaf(h.y, w, acc.y);
        acc.z = fmaf(h.z, w, acc.z); acc.w = fmaf(h.w, w, acc.w);
    }
    *(float4*)(out + (size_t)node * 128 + lane * 4) = acc;
}
__global__ void k_agg64(const int* __restrict__ offs, const int* __restrict__ csrc,
                        const float* __restrict__ cnorm, const float* __restrict__ H,
                        const float* __restrict__ invdeg,
                        const float* __restrict__ b0, const float* __restrict__ b1,
                        float* __restrict__ out, int N, int N2) {
    int node = blockIdx.x * (blockDim.x >> 5) + (threadIdx.x >> 5);
    int lane = threadIdx.x & 31;
    if (node >= N2) return;
    const float* bias = (node >= N) ? b1 : b0;
    float id = invdeg[node];
    float2 acc = *(const float2*)(H + (size_t)node * 64 + lane * 2);
    float2 b = *(const float2*)(bias + lane * 2);
    acc.x = fmaf(acc.x, id, b.x); acc.y = fmaf(acc.y, id, b.y);
    int beg = offs[node], end = offs[node + 1];
    for (int j = beg; j < end; j++) {
        int s = __ldg(&csrc[j]);
        float w = __ldg(&cnorm[j]);
        float2 h = *(const float2*)(H + (size_t)s * 64 + lane * 2);
        acc.x = fmaf(h.x, w, acc.x); acc.y = fmaf(h.y, w, acc.y);
    }
    *(float2*)(out + (size_t)node * 64 + lane * 2) = acc;
}

// ---------------- BN stats (raw sums) ----------------
__global__ void k_bnstats(const float* __restrict__ A, float* __restrict__ stats,
                          int stride, int nbb, int Nloc, int M) {
    int branch = (blockIdx.x >= nbb) ? 1 : 0;
    int blk = blockIdx.x - branch * nbb;
    int c = threadIdx.x;
    int row0 = blk * 64;
    int rend = min(row0 + 64, Nloc);
    const float* Ab = A + (size_t)branch * Nloc * M;
    float* st = stats + branch * stride;
    float s = 0.f, sq = 0.f;
    for (int r = row0; r < rend; r++) {
        float v = Ab[(size_t)r * M + c];
        s += v;
        sq += v * v;
    }
    atomicAdd(st + c, s);
    atomicAdd(st + M + c, sq);
}

// BN+ReLU + mean-pool; scale/shift computed inline from raw sums
__global__ void k_bnrelu_pool(const float* __restrict__ A,
                              const float* __restrict__ statsL2,  // = stats + 1024
                              const float* __restrict__ ga0, const float* __restrict__ be0,
                              const float* __restrict__ ga1, const float* __restrict__ be1,
                              float inv_n,
                              const int* __restrict__ batch, float* __restrict__ pool,
                              int N, int N2, int G) {
    int idx = blockIdx.x * blockDim.x + threadIdx.x;
    if (idx >= N2 * 64) return;
    int node = idx >> 6, c = idx & 63;
    int branch = (node >= N) ? 1 : 0;
    int ln = node - branch * N;
    const float* st = statsL2 + branch * 256;
    const float* ga = branch ? ga1 : ga0;
    const float* be = branch ? be1 : be0;
    float mean = st[c] * inv_n;
    float var = st[64 + c] * inv_n - mean * mean;
    float sc = ga[c] * rsqrtf(var + 1e-5f);
    float sh = be[c] - mean * sc;
    float v = fmaxf(fmaf(A[idx], sc, sh), 0.f);
    atomicAdd(&pool[branch * G * 64 + batch[ln] * 64 + c], v);
}

// head GEMM with fused concat+mean: X row g = [pool_c[g]|pool_s[g]] / cnt[g]
__global__ void k_gemmHead(const float* __restrict__ pool, const float* __restrict__ cnt,
                           const float* __restrict__ Wf1, const float* __restrict__ bf1,
                           float* __restrict__ H, int G) {
    constexpr int R = 32;
    __shared__ float xs[R * 128];
    int row0 = blockIdx.x * R;
    for (int i = threadIdx.x; i < R * 128; i += 128) {
        int r = i >> 7, k = i & 127;
        int row = row0 + r;
        float v = 0.f;
        if (row < G) {
            float inv = 1.f / fmaxf(cnt[row], 1.f);
            v = ((k < 64) ? pool[row * 64 + k] : pool[G * 64 + row * 64 + (k - 64)]) * inv;
        }
        xs[i] = v;
    }
    __syncthreads();

    int col = threadIdx.x & 63;
    int rbase = (threadIdx.x >> 6) * 16;
    float bb = bf1[col];
    float acc[16];
#pragma unroll
    for (int r = 0; r < 16; r++) acc[r] = bb;

    for (int kc = 0; kc < 128; kc += 32) {
        float w[32];
#pragma unroll
        for (int kk = 0; kk < 32; kk++) w[kk] = Wf1[(kc + kk) * 64 + col];
#pragma unroll
        for (int r = 0; r < 16; r++) {
            const float4* xr = (const float4*)(xs + (rbase + r) * 128 + kc);
#pragma unroll
            for (int q = 0; q < 8; q++) {
                float4 xv = xr[q];
                acc[r] = fmaf(xv.x, w[4 * q + 0], acc[r]);
                acc[r] = fmaf(xv.y, w[4 * q + 1], acc[r]);
                acc[r] = fmaf(xv.z, w[4 * q + 2], acc[r]);
                acc[r] = fmaf(xv.w, w[4 * q + 3], acc[r]);
            }
        }
    }
#pragma unroll
    for (int r = 0; r < 16; r++) {
        int row = row0 + rbase + r;
        if (row < G) H[(size_t)row * 64 + col] = acc[r];
    }
}

// head output: BN scale/shift from raw sums (smem precompute) + ReLU + dot(Wf2)
__global__ void k_headout(const float* __restrict__ T,
                          const float* __restrict__ statsH,  // = stats + 1536
                          const float* __restrict__ gf1, const float* __restrict__ bef1,
                          const float* __restrict__ Wf2, const float* __restrict__ bf2,
                          float inv_g, float* __restrict__ out, int G) {
    __shared__ float scs[64], shs[64], wf[64];
    if (threadIdx.x < 64) {
        int c = threadIdx.x;
        float mean = statsH[c] * inv_g;
        float var = statsH[64 + c] * inv_g - mean * mean;
        float sc = gf1[c] * rsqrtf(var + 1e-5f);
        scs[c] = sc;
        shs[c] = bef1[c] - mean * sc;
        wf[c] = Wf2[c];
    }
    __syncthreads();
    int g = blockIdx.x * blockDim.x + threadIdx.x;
    if (g >= G) return;
    float acc = bf2[0];
#pragma unroll 8
    for (int j = 0; j < 64; j++) {
        float v = fmaxf(fmaf(T[g * 64 + j], scs[j], shs[j]), 0.f);
        acc = fmaf(v, wf[j], acc);
    }
    out[g] = acc;
}

// ---------------- host ----------------
static inline int ceil_div(int a, int b) { return (a + b - 1) / b; }

extern "C" void kernel_launch(void* const* d_in, const int* in_sizes, int n_in,
                              void* d_out, int out_size) {
    const float* xc   = (const float*)d_in[0];
    const float* xs_  = (const float*)d_in[1];
    const int*   eic  = (const int*)d_in[2];
    const int*   eis  = (const int*)d_in[3];
    const int*   batch= (const int*)d_in[4];
    const float* W1c = (const float*)d_in[5],  *b1c = (const float*)d_in[6];
    const float* g1c = (const float*)d_in[7],  *be1c= (const float*)d_in[8];
    const float* W2c = (const float*)d_in[9],  *b2c = (const float*)d_in[10];
    const float* g2c = (const float*)d_in[11], *be2c= (const float*)d_in[12];
    const float* W1s = (const float*)d_in[13], *b1s = (const float*)d_in[14];
    const float* g1s = (const float*)d_in[15], *be1s= (const float*)d_in[16];
    const float* W2s = (const float*)d_in[17], *b2s = (const float*)d_in[18];
    const float* g2s = (const float*)d_in[19], *be2s= (const float*)d_in[20];
    const float* Wf1 = (const float*)d_in[21], *bf1 = (const float*)d_in[22];
    const float* gf1 = (const float*)d_in[23], *bef1= (const float*)d_in[24];
    const float* Wf2 = (const float*)d_in[25], *bf2 = (const float*)d_in[26];

    const int N = in_sizes[0] / 64;
    const int E = in_sizes[2] / 2;
    const int G = out_size;
    const int N2 = 2 * N;
    const int E2 = 2 * E;
    const float invN = 1.f / (float)N;
    const float invG = 1.f / (float)G;

    float *bufA, *bufB, *dinv, *invdeg, *stats, *pool, *cnt, *headT, *cnorm;
    int *deg, *offs, *cursor, *bsum, *bscan, *csrc;
    cudaGetSymbolAddress((void**)&bufA, g_bufA);
    cudaGetSymbolAddress((void**)&bufB, g_bufB);
    cudaGetSymbolAddress((void**)&deg, g_deg);
    cudaGetSymbolAddress((void**)&dinv, g_dinv);
    cudaGetSymbolAddress((void**)&invdeg, g_invdeg);
    cudaGetSymbolAddress((void**)&offs, g_offs);
    cudaGetSymbolAddress((void**)&cursor, g_cursor);
    cudaGetSymbolAddress((void**)&bsum, g_bsum);
    cudaGetSymbolAddress((void**)&bscan, g_bscan);
    cudaGetSymbolAddress((void**)&csrc, g_csrc);
    cudaGetSymbolAddress((void**)&cnorm, g_cnorm);
    cudaGetSymbolAddress((void**)&stats, g_stats);
    cudaGetSymbolAddress((void**)&pool, g_pool);
    cudaGetSymbolAddress((void**)&cnt, g_cnt);
    cudaGetSymbolAddress((void**)&headT, g_headT);

    const int nbScan = ceil_div(N2, 256);
    const int zeroTotal = N2 + 2048 + 2 * G * 64 + G;
    const bool fork = g_hx.ok;
    cudaStream_t sB = fork ? g_hx.s2 : (cudaStream_t)0;

    // ---- side chain (CSR build + zero-init), overlapped with GEMM1 if possible
    if (fork) {
        cudaEventRecord(g_hx.evFork, 0);
        cudaStreamWaitEvent(sB, g_hx.evFork, 0);
    }
    k_zero_all<<<ceil_div(zeroTotal, 256), 256, 0, sB>>>(deg, N2, stats, 2048,
                                                         pool, 2 * G * 64, cnt, G);
    k_hist<<<ceil_div(N + E2, 256), 256, 0, sB>>>(batch, N, eic, eis, E, cnt, deg);
    k_scan1<<<nbScan, 256, 0, sB>>>(deg, offs, bsum, dinv, invdeg, N2);
    k_scan2<<<1, 512, 0, sB>>>(bsum, bscan, nbScan);
    k_scan3<<<ceil_div(N2, 256), 256, 0, sB>>>(offs, cursor, bscan, N2, E2);
    k_fill2<<<ceil_div(E2, 256), 256, 0, sB>>>(eic, eis, E, N, dinv, cursor, csrc, cnorm);
    if (fork) cudaEventRecord(g_hx.evJoin, sB);

    const int nbbL1 = ceil_div(N, 16);   // GEMM1 R=16, M=128
    const int nbbL2 = ceil_div(N, 32);   // GEMM2 R=32, M=64
    const int nbbBN = ceil_div(N, 64);

    // ---- layer 1 GEMM (independent of CSR chain) ----
    k_gemm2<64, 128, 16, false><<<2 * nbbL1, 128>>>(xc, xs_, W1c, W1s,
                                                    nullptr, 0, nullptr, nullptr,
                                                    nullptr, nullptr, 0.f,
                                                    bufB, N, nbbL1);
    if (fork) cudaStreamWaitEvent(0, g_hx.evJoin, 0);

    // ---- layer 1 agg + stats ----
    k_agg128<<<ceil_div(N2, 8), 256>>>(offs, csrc, cnorm, bufB, invdeg, b1c, b1s, bufA, N, N2);
    k_bnstats<<<2 * nbbBN, 128>>>(bufA, stats, 512, nbbBN, N, 128);

    // ---- layer 2: 128 -> 64 (BN+ReLU from raw sums fused into GEMM input) ----
    k_gemm2<128, 64, 32, true><<<2 * nbbL2, 128>>>(bufA, bufA + (size_t)N * 128, W2c, W2s,
                                                   stats, 512, g1c, be1c, g1s, be1s, invN,
                                                   bufB, N, nbbL2);
    k_agg64<<<ceil_div(N2, 8), 256>>>(offs, csrc, cnorm, bufB, invdeg, b2c, b2s, bufA, N, N2);
    k_bnstats<<<2 * nbbBN, 64>>>(bufA, stats + 1024, 256, nbbBN, N, 64);

    // ---- BN+ReLU + mean pool (scale/shift inline) ----
    k_bnrelu_pool<<<ceil_div(N2 * 64, 256), 256>>>(bufA, stats + 1024,
                                                   g2c, be2c, g2s, be2s, invN,
                                                   batch, pool, N, N2, G);

    // ---- head ----
    k_gemmHead<<<ceil_div(G, 32), 128>>>(pool, cnt, Wf1, bf1, headT, G);
    const int nbbHS = ceil_div(G, 64);
    k_bnstats<<<nbbHS, 64>>>(headT, stats + 1536, 0, nbbHS, G, 64);
    k_headout<<<ceil_div(G, 256), 256>>>(headT, stats + 1536, gf1, bef1, Wf2, bf2,
                                         invG, (float*)d_out, G);
}